// round 13
// baseline (speedup 1.0000x reference)
#include <cuda_runtime.h>

// Inverse 2D DWT, L=2 separable synthesis, stride 2, pad 0 -> per input
// pixel a 2x2 butterfly into the output.
//
// Fully 256-bit variant (Blackwell): one thread per (input row, 8-col group).
//   Loads : 4x LDG.256 (ld.global.v8.f32, one per plane)  -> 32B/lane
//   Stores: 4x STG.256 (st.global.cs.v8.f32)              -> 32B/lane
// 256 B of DRAM traffic per thread; every memory instruction is lane-maximal.
// Grid (H*W/8/256, NC); no integer division; all 32-bit offsets.

__global__ void __launch_bounds__(256)
idwt2_l2_kernel(const float* __restrict__ low,
                const float* __restrict__ highs,
                const float* __restrict__ g0c_p,
                const float* __restrict__ g1c_p,
                const float* __restrict__ g0r_p,
                const float* __restrict__ g1r_p,
                float* __restrict__ out)
{
    constexpr int H  = 256, W = 256;
    constexpr int PLANE  = H * W;          // 65536
    constexpr int Wo     = 2 * W;          // 512
    constexpr int OPLANE = 4 * PLANE;      // 262144

    // Uniform filter taps (broadcast).
    const float a0 = __ldg(&g0c_p[0]), a1 = __ldg(&g0c_p[1]);
    const float b0 = __ldg(&g1c_p[0]), b1 = __ldg(&g1c_p[1]);
    const float c0 = __ldg(&g0r_p[0]), c1 = __ldg(&g0r_p[1]);
    const float d0 = __ldg(&g1r_p[0]), d1 = __ldg(&g1r_p[1]);

    const int nc  = blockIdx.y;
    const int pos = blockIdx.x * 256 + threadIdx.x;   // 0 .. H*W/8 - 1
    const int i   = pos >> 5;                         // input row
    const int j8  = pos & 31;                         // 8-col group

    const unsigned rowoff = (unsigned)i * W + (unsigned)(j8 << 3);
    const unsigned loff   = (unsigned)nc * PLANE + rowoff;
    const unsigned hb     = (unsigned)nc * (3 * PLANE) + rowoff;

    // 256-bit loads: 8 floats per plane.
    float ll[8], lh[8], hl[8], hh[8];
    #define LDG256(DST, PTR)                                                  \
        asm volatile(                                                         \
            "ld.global.v8.f32 {%0, %1, %2, %3, %4, %5, %6, %7}, [%8];"        \
            : "=f"((DST)[0]), "=f"((DST)[1]), "=f"((DST)[2]), "=f"((DST)[3]), \
              "=f"((DST)[4]), "=f"((DST)[5]), "=f"((DST)[6]), "=f"((DST)[7])  \
            : "l"(PTR))
    LDG256(ll, low   + loff);
    LDG256(lh, highs + hb);
    LDG256(hl, highs + hb + PLANE);
    LDG256(hh, highs + hb + 2 * PLANE);
    #undef LDG256

    // r0: output row 2i (16 cols), r1: output row 2i+1.
    float r0[16], r1[16];
    #pragma unroll
    for (int k = 0; k < 8; ++k) {
        const float A0 = ll[k] * a0 + lh[k] * b0;
        const float B0 = hl[k] * a0 + hh[k] * b0;
        const float A1 = ll[k] * a1 + lh[k] * b1;
        const float B1 = hl[k] * a1 + hh[k] * b1;
        r0[2 * k]     = A0 * c0 + B0 * d0;
        r0[2 * k + 1] = A0 * c1 + B0 * d1;
        r1[2 * k]     = A1 * c0 + B1 * d0;
        r1[2 * k + 1] = A1 * c1 + B1 * d1;
    }

    const unsigned ooff = (unsigned)nc * OPLANE
                        + (unsigned)(2 * i) * Wo
                        + (unsigned)(j8 << 4);

    #define STG256(PTR, SRC)                                                  \
        asm volatile(                                                         \
            "st.global.cs.v8.f32 [%0], {%1, %2, %3, %4, %5, %6, %7, %8};"     \
            :: "l"(PTR),                                                      \
               "f"((SRC)[0]), "f"((SRC)[1]), "f"((SRC)[2]), "f"((SRC)[3]),    \
               "f"((SRC)[4]), "f"((SRC)[5]), "f"((SRC)[6]), "f"((SRC)[7])     \
            : "memory")
    STG256(out + ooff,           r0);      // row 2i,   cols [16j8, 16j8+8)
    STG256(out + ooff + 8,       r0 + 8);  // row 2i,   cols [16j8+8, 16j8+16)
    STG256(out + ooff + Wo,      r1);      // row 2i+1
    STG256(out + ooff + Wo + 8,  r1 + 8);
    #undef STG256
}

extern "C" void kernel_launch(void* const* d_in, const int* in_sizes, int n_in,
                              void* d_out, int out_size)
{
    const float* low   = (const float*)d_in[0];
    const float* highs = (const float*)d_in[1];
    const float* g0c   = (const float*)d_in[2];
    const float* g1c   = (const float*)d_in[3];
    const float* g0r   = (const float*)d_in[4];
    const float* g1r   = (const float*)d_in[5];
    float* out = (float*)d_out;

    const int H = 256, W = 256;
    const int NC = in_sizes[0] / (H * W);

    dim3 grid((H * (W / 8)) / 256, NC);    // (32, NC)
    idwt2_l2_kernel<<<grid, 256>>>(low, highs, g0c, g1c, g0r, g1r, out);
}

// round 14
// speedup vs baseline: 1.0023x; 1.0023x over previous
#include <cuda_runtime.h>

// Inverse 2D DWT, L=2 separable synthesis, stride 2, pad 0 -> per input
// pixel a 2x2 butterfly into the output.
//
// Champion structure (R12) with default-policy stores:
//   one thread per (input row, float4-col-group)
//   Loads : 4x LDG.128 (one float4 per plane)        -> 16B/lane
//   Stores: 2x STG.256 (st.global.v8.f32, no hint)   -> 32B/lane
// Grid (H*W/4/256, NC); no integer division; all 32-bit offsets.

__global__ void __launch_bounds__(256)
idwt2_l2_kernel(const float* __restrict__ low,
                const float* __restrict__ highs,
                const float* __restrict__ g0c_p,
                const float* __restrict__ g1c_p,
                const float* __restrict__ g0r_p,
                const float* __restrict__ g1r_p,
                float* __restrict__ out)
{
    constexpr int H  = 256, W = 256;
    constexpr int PLANE  = H * W;          // 65536
    constexpr int Wo     = 2 * W;          // 512
    constexpr int OPLANE = 4 * PLANE;      // 262144

    // Uniform filter taps (broadcast).
    const float a0 = __ldg(&g0c_p[0]), a1 = __ldg(&g0c_p[1]);
    const float b0 = __ldg(&g1c_p[0]), b1 = __ldg(&g1c_p[1]);
    const float c0 = __ldg(&g0r_p[0]), c1 = __ldg(&g0r_p[1]);
    const float d0 = __ldg(&g1r_p[0]), d1 = __ldg(&g1r_p[1]);

    const int nc  = blockIdx.y;
    const int pos = blockIdx.x * 256 + threadIdx.x;   // 0 .. H*W/4 - 1
    const int i   = pos >> 6;                         // input row
    const int j4  = pos & 63;                         // float4 column group

    const unsigned rowoff = (unsigned)i * W + (unsigned)(j4 << 2);
    const unsigned loff   = (unsigned)nc * PLANE + rowoff;
    const unsigned hb     = (unsigned)nc * (3 * PLANE) + rowoff;

    const float4 ll = *reinterpret_cast<const float4*>(low   + loff);
    const float4 lh = *reinterpret_cast<const float4*>(highs + hb);
    const float4 hl = *reinterpret_cast<const float4*>(highs + hb + PLANE);
    const float4 hh = *reinterpret_cast<const float4*>(highs + hb + 2 * PLANE);

    // r0[0..7]: output row 2i, cols 8*j4 .. 8*j4+7
    // r1[0..7]: output row 2i+1, same cols
    float r0[8], r1[8];

    #define COL(LLC, LHC, HLC, HHC, O)                                        \
    {                                                                         \
        const float A0 = (LLC) * a0 + (LHC) * b0;                             \
        const float B0 = (HLC) * a0 + (HHC) * b0;                             \
        const float A1 = (LLC) * a1 + (LHC) * b1;                             \
        const float B1 = (HLC) * a1 + (HHC) * b1;                             \
        r0[(O)]     = A0 * c0 + B0 * d0;  r0[(O) + 1] = A0 * c1 + B0 * d1;    \
        r1[(O)]     = A1 * c0 + B1 * d0;  r1[(O) + 1] = A1 * c1 + B1 * d1;    \
    }

    COL(ll.x, lh.x, hl.x, hh.x, 0)
    COL(ll.y, lh.y, hl.y, hh.y, 2)
    COL(ll.z, lh.z, hl.z, hh.z, 4)
    COL(ll.w, lh.w, hl.w, hh.w, 6)
    #undef COL

    const unsigned ooff = (unsigned)nc * OPLANE
                        + (unsigned)(2 * i) * Wo
                        + (unsigned)(j4 << 3);

    // 256-bit stores, default cache policy.
    asm volatile(
        "st.global.v8.f32 [%0], {%1, %2, %3, %4, %5, %6, %7, %8};"
        :: "l"(out + ooff),
           "f"(r0[0]), "f"(r0[1]), "f"(r0[2]), "f"(r0[3]),
           "f"(r0[4]), "f"(r0[5]), "f"(r0[6]), "f"(r0[7])
        : "memory");
    asm volatile(
        "st.global.v8.f32 [%0], {%1, %2, %3, %4, %5, %6, %7, %8};"
        :: "l"(out + ooff + Wo),
           "f"(r1[0]), "f"(r1[1]), "f"(r1[2]), "f"(r1[3]),
           "f"(r1[4]), "f"(r1[5]), "f"(r1[6]), "f"(r1[7])
        : "memory");
}

extern "C" void kernel_launch(void* const* d_in, const int* in_sizes, int n_in,
                              void* d_out, int out_size)
{
    const float* low   = (const float*)d_in[0];
    const float* highs = (const float*)d_in[1];
    const float* g0c   = (const float*)d_in[2];
    const float* g1c   = (const float*)d_in[3];
    const float* g0r   = (const float*)d_in[4];
    const float* g1r   = (const float*)d_in[5];
    float* out = (float*)d_out;

    const int H = 256, W = 256;
    const int NC = in_sizes[0] / (H * W);

    dim3 grid((H * (W / 4)) / 256, NC);    // (64, NC)
    idwt2_l2_kernel<<<grid, 256>>>(low, highs, g0c, g1c, g0r, g1r, out);
}